// round 17
// baseline (speedup 1.0000x reference)
#include <cuda_runtime.h>
#include <cstdint>

// SoftTree: x[4096,512], gw[512,255], gb[255], pw[64,512,256], pb[64,256]
// out[b,o] = sum_l leafp[b,l] * ((x @ pw[o])[b,l] + pb[o,l])
//
// R17 = R16 (warp-decoupled GEMM) + TAIL-RACE FIX:
//   final K-stage peeled and guarded by cp.async.wait_group 0. R16's
//   wait_group 1 at st=31 left stage 31's own group pending -> read of
//   incomplete smem -> rel_err 7.4e-3.
// Everything else identical to R16: per-warp private 3-stage rings (A tile
// duplicated per warp + own B quarter), no __syncthreads in main loop,
// 2 CTAs/SM, CTA 64x256, 4 warps, warp tile 64x64, BK=16.

#define N_BATCH   4096
#define N_IN      512
#define N_OUT     64
#define N_LEAF    256
#define N_GATE    255
#define TREE_DEPTH 8

__device__ float  d_leafp[N_BATCH * N_LEAF];                 // 4 MB
__device__ float4 d_xt2[(N_BATCH / 128) * 16 * 1024];        // 8 MB  (A quads)
__device__ float2 d_pwp[(size_t)N_OUT * 16 * 4096];          // 33.5 MB (B pairs)

__device__ __forceinline__ float rna_tf32(float f) {
    uint32_t u;
    asm("cvt.rna.tf32.f32 %0, %1;" : "=r"(u) : "f"(f));
    return __uint_as_float(u);
}
__device__ __forceinline__ uint32_t smem_u32(const void* p) {
    uint32_t a;
    asm("{ .reg .u64 t; cvta.to.shared.u64 t, %1; cvt.u32.u64 %0, t; }"
        : "=r"(a) : "l"(p));
    return a;
}

#define CP_ASYNC16(dst_u32, src_ptr) \
    asm volatile("cp.async.cg.shared.global [%0], [%1], 16;" \
                 :: "r"(dst_u32), "l"(src_ptr))
#define CP_COMMIT()  asm volatile("cp.async.commit_group;" ::: "memory")
#define CP_WAIT1()   asm volatile("cp.async.wait_group 1;" ::: "memory")
#define CP_WAIT0()   asm volatile("cp.async.wait_group 0;" ::: "memory")

__device__ __forceinline__ void mma_tf32(float* d, const uint32_t* a,
                                         const uint32_t* b) {
    asm volatile(
        "mma.sync.aligned.m16n8k8.row.col.f32.tf32.tf32.f32 "
        "{%0,%1,%2,%3}, {%4,%5,%6,%7}, {%8,%9}, {%0,%1,%2,%3};"
        : "+f"(d[0]), "+f"(d[1]), "+f"(d[2]), "+f"(d[3])
        : "r"(a[0]), "r"(a[1]), "r"(a[2]), "r"(a[3]), "r"(b[0]), "r"(b[1]));
}

// ---------------------------------------------------------------------------
// P0: x -> A-frag quads.
// ---------------------------------------------------------------------------
__global__ __launch_bounds__(256) void xt2_kernel(const float* __restrict__ x) {
    const int kt = blockIdx.x, bt = blockIdx.y;
    #pragma unroll
    for (int it = 0; it < 4; ++it) {
        int qid = it * 256 + threadIdx.x;
        int mb = qid >> 7, ks = (qid >> 5) & 3, lq = (qid >> 2) & 7, lr = qid & 3;
        int b = bt * 128 + mb * 16 + lq;
        int k = kt * 32 + ks * 8 + lr;
        const float* xb = x + (size_t)b * N_IN + k;
        float4 q;
        q.x = rna_tf32(xb[0]);
        q.y = rna_tf32(xb[8 * N_IN]);
        q.z = rna_tf32(xb[4]);
        q.w = rna_tf32(xb[8 * N_IN + 4]);
        d_xt2[(size_t)(bt * 16 + kt) * 1024 + qid] = q;
    }
}

// ---------------------------------------------------------------------------
// P1: pw -> B-frag pairs (coalesced 2x float4 stores).
// ---------------------------------------------------------------------------
__global__ __launch_bounds__(256) void pwp_kernel(const float* __restrict__ pw) {
    const int o = blockIdx.y;
    const int kt = blockIdx.x >> 2, ks = blockIdx.x & 3;
    const int n = threadIdx.x;
    const int k0 = kt * 32 + ks * 8;
    const float* src = pw + ((size_t)o * N_IN + k0) * N_LEAF + n;
    float v[8];
    #pragma unroll
    for (int j = 0; j < 8; ++j) v[j] = rna_tf32(src[j * N_LEAF]);
    float4* dst = reinterpret_cast<float4*>(
        d_pwp + ((size_t)(o * 16 + kt) * 4 + ks) * 1024 + n * 4);
    dst[0] = make_float4(v[0], v[4], v[1], v[5]);
    dst[1] = make_float4(v[2], v[6], v[3], v[7]);
}

// ---------------------------------------------------------------------------
// K2: gates + leaf probabilities
// ---------------------------------------------------------------------------
#define K1_ROWS 8
__global__ __launch_bounds__(256) void softtree_gates_kernel(
    const float* __restrict__ x, const float* __restrict__ gw,
    const float* __restrict__ gb)
{
    __shared__ float xs[K1_ROWS][N_IN];
    __shared__ float gs[K1_ROWS][N_LEAF];
    const int tid = threadIdx.x;
    const int b0  = blockIdx.x * K1_ROWS;

    {
        const float4* src = reinterpret_cast<const float4*>(x + (size_t)b0 * N_IN);
        float4* dst = reinterpret_cast<float4*>(&xs[0][0]);
        #pragma unroll
        for (int it = 0; it < (K1_ROWS * N_IN / 4) / 256; ++it)
            dst[it * 256 + tid] = src[it * 256 + tid];
    }
    __syncthreads();

    if (tid < N_GATE) {
        float acc[K1_ROWS];
        const float bias = gb[tid];
        #pragma unroll
        for (int r = 0; r < K1_ROWS; ++r) acc[r] = bias;
        #pragma unroll 4
        for (int i = 0; i < N_IN; ++i) {
            float w = gw[i * N_GATE + tid];
            #pragma unroll
            for (int r = 0; r < K1_ROWS; ++r)
                acc[r] = fmaf(xs[r][i], w, acc[r]);
        }
        #pragma unroll
        for (int r = 0; r < K1_ROWS; ++r)
            gs[r][tid] = 1.0f / (1.0f + expf(-acc[r]));
    }
    __syncthreads();

    const int l = tid;
    #pragma unroll
    for (int r = 0; r < K1_ROWS; ++r) {
        float p = 1.0f;
        int index = 1;
        #pragma unroll
        for (int j = 0; j < TREE_DEPTH; ++j) {
            int bit = (l >> (TREE_DEPTH - 1 - j)) & 1;
            float g = gs[r][index - 1];
            p *= bit ? (1.0f - g) : g;
            index = 2 * index + bit;
        }
        d_leafp[(size_t)(b0 + r) * N_LEAF + l] = p;
    }
}

// ---------------------------------------------------------------------------
// GEMM: tf32 mma.sync, warp-decoupled 3-stage private rings, no CTA barrier
// in the main loop. Grid (64 bt64, 64 o), 128 threads (4 warps, 1m x 4n).
// Per-warp stage buffer: A full tile 1024 floats + B quarter 1024 floats.
// Smem/CTA: 4 warps * 3 stages * 2048 floats + red = 99,328 B (2 CTAs/SM).
// ---------------------------------------------------------------------------
#define WST_F   2048
#define WRING_F (3 * WST_F)
#define SMEM_FLOATS (4 * WRING_F + 4 * 64)
#define N_KT 32

__device__ __forceinline__ void load_stage_w(
    uint32_t a_base, uint32_t b_base,
    const float4* __restrict__ xa_h, const float2* __restrict__ bb_st,
    int wn, int lane)
{
    #pragma unroll
    for (int i = 0; i < 8; ++i) {
        int dstq = 32 * i + lane;
        int srcq = (i >> 1) * 128 + (i & 1) * 32 + lane;
        CP_ASYNC16(a_base + (uint32_t)dstq * 16, xa_h + srcq);
    }
    #pragma unroll
    for (int i = 0; i < 8; ++i) {
        int ks2 = i >> 2;
        int within = 32 * (i & 3) + lane;
        CP_ASYNC16(b_base + (uint32_t)(ks2 * 2048 + within * 16),
                   bb_st + ks2 * 1024 + wn * 256 + within * 2);
    }
    CP_COMMIT();
}

__global__ __launch_bounds__(128, 2) void softtree_gemm_mma(
    const float* __restrict__ pb, float* __restrict__ out)
{
    extern __shared__ float sm[];
    float* red = sm + 4 * WRING_F;   // [4][64]

    const int tid  = threadIdx.x;
    const int lane = tid & 31;
    const int wn   = tid >> 5;
    const int lq   = lane >> 2;
    const int lr   = lane & 3;
    const int o    = blockIdx.y;
    const int bt64 = blockIdx.x;
    const int b0   = bt64 * 64;

    const float4* __restrict__ xa_all =
        d_xt2 + ((size_t)(bt64 >> 1) * 16) * 1024 + (bt64 & 1) * 512;
    const float2* __restrict__ bb_all = d_pwp + (size_t)o * 16 * 4096;

    float* wbuf = sm + wn * WRING_F;
    const uint32_t wbase = smem_u32(wbuf);

    float acc[4][8][4];
    #pragma unroll
    for (int mf = 0; mf < 4; ++mf)
        #pragma unroll
        for (int nf = 0; nf < 8; ++nf)
            #pragma unroll
            for (int e = 0; e < 4; ++e) acc[mf][nf][e] = 0.0f;

    auto load_st = [&](int st, int slot) {
        const int kt32 = st >> 1, h = st & 1;
        load_stage_w(wbase + (uint32_t)slot * (WST_F * 4),
                     wbase + (uint32_t)slot * (WST_F * 4) + 4096,
                     xa_all + kt32 * 1024 + h * 64,
                     bb_all + (size_t)(kt32 * 4 + 2 * h) * 1024,
                     wn, lane);
    };

    auto compute_stage = [&](const float* Asb) {
        const float* Bsb = Asb + 1024;
        #pragma unroll
        for (int ks2 = 0; ks2 < 2; ++ks2) {
            uint32_t af[4][4], bf[8][2];
            #pragma unroll
            for (int mf = 0; mf < 4; ++mf) {
                float4 a4 = *reinterpret_cast<const float4*>(
                    Asb + ((size_t)(mf * 64 + ks2 * 32 + lq * 4 + lr)) * 4);
                af[mf][0] = __float_as_uint(a4.x);
                af[mf][1] = __float_as_uint(a4.y);
                af[mf][2] = __float_as_uint(a4.z);
                af[mf][3] = __float_as_uint(a4.w);
            }
            #pragma unroll
            for (int nf = 0; nf < 8; ++nf) {
                float2 b2 = *reinterpret_cast<const float2*>(
                    Bsb + ((size_t)(ks2 * 256 + (nf * 8 + lq) * 4 + lr)) * 2);
                bf[nf][0] = __float_as_uint(b2.x);
                bf[nf][1] = __float_as_uint(b2.y);
            }
            #pragma unroll
            for (int mf = 0; mf < 4; ++mf)
                #pragma unroll
                for (int nf = 0; nf < 8; ++nf)
                    mma_tf32(acc[mf][nf], af[mf], bf[nf]);
        }
    };

    // Per-warp pipeline: prologue 2 stages; loop over 31 stages with WAIT1
    // (stage st guaranteed: most recent committed group is st+1); final
    // stage peeled with WAIT0 (drain all — fixes R16's tail race).
    load_st(0, 0);
    load_st(1, 1);

    int slot = 0;
    #pragma unroll 1
    for (int st = 0; st < N_KT - 1; ++st) {
        CP_WAIT1();
        __syncwarp();
        compute_stage(wbuf + slot * WST_F);
        if (st + 2 < N_KT) {
            int nslot = slot + 2; if (nslot >= 3) nslot -= 3;
            load_st(st + 2, nslot);
        }
        if (++slot == 3) slot = 0;
    }
    CP_WAIT0();          // final stage: ALL groups complete
    __syncwarp();
    compute_stage(wbuf + slot * WST_F);

    // Fused epilogue: s[row] = sum_n p[b,n]*(C[b,n] + pb[o,n])
    const float* __restrict__ pbo = pb + (size_t)o * N_LEAF;
    #pragma unroll
    for (int mf = 0; mf < 4; ++mf) {
        const int r0 = mf * 16 + lq;
        const int r1 = r0 + 8;
        const float* p0row = d_leafp + (size_t)(b0 + r0) * N_LEAF;
        const float* p1row = d_leafp + (size_t)(b0 + r1) * N_LEAF;
        float s0 = 0.0f, s1 = 0.0f;
        #pragma unroll
        for (int nf = 0; nf < 8; ++nf) {
            const int n = wn * 64 + nf * 8 + 2 * lr;
            float2 pbv = *reinterpret_cast<const float2*>(pbo + n);
            float2 pa  = *reinterpret_cast<const float2*>(p0row + n);
            float2 pc  = *reinterpret_cast<const float2*>(p1row + n);
            s0 = fmaf(acc[mf][nf][0] + pbv.x, pa.x, s0);
            s0 = fmaf(acc[mf][nf][1] + pbv.y, pa.y, s0);
            s1 = fmaf(acc[mf][nf][2] + pbv.x, pc.x, s1);
            s1 = fmaf(acc[mf][nf][3] + pbv.y, pc.y, s1);
        }
        s0 += __shfl_xor_sync(0xffffffffu, s0, 1);
        s0 += __shfl_xor_sync(0xffffffffu, s0, 2);
        s1 += __shfl_xor_sync(0xffffffffu, s1, 1);
        s1 += __shfl_xor_sync(0xffffffffu, s1, 2);
        if (lr == 0) {
            red[wn * 64 + r0] = s0;
            red[wn * 64 + r1] = s1;
        }
    }
    __syncthreads();

    if (tid < 64) {
        float v = red[0 * 64 + tid] + red[1 * 64 + tid] +
                  red[2 * 64 + tid] + red[3 * 64 + tid];
        out[(size_t)(b0 + tid) * N_OUT + o] = v;
    }
}

// ---------------------------------------------------------------------------
extern "C" void kernel_launch(void* const* d_in, const int* in_sizes, int n_in,
                              void* d_out, int out_size)
{
    const float* x  = (const float*)d_in[0];
    const float* gw = (const float*)d_in[1];
    const float* gb = (const float*)d_in[2];
    const float* pw = (const float*)d_in[3];
    const float* pb = (const float*)d_in[4];
    float* out = (float*)d_out;

    const int smem_bytes = SMEM_FLOATS * 4;     // 99,328 B per CTA
    cudaFuncSetAttribute(softtree_gemm_mma,
                         cudaFuncAttributeMaxDynamicSharedMemorySize, smem_bytes);

    xt2_kernel<<<dim3(16, 32), 256>>>(x);
    pwp_kernel<<<dim3(64, 64), 256>>>(pw);
    softtree_gates_kernel<<<N_BATCH / K1_ROWS, 256>>>(x, gw, gb);

    dim3 grid(N_BATCH / 64, N_OUT);
    softtree_gemm_mma<<<grid, 128, smem_bytes>>>(pb, out);
}